// round 6
// baseline (speedup 1.0000x reference)
#include <cuda_runtime.h>
#include <cstdint>

// ---------------- problem constants ----------------
#define N_NODES 8192
#define IN_DIM  64
#define OUT_DIM 64
#define SUPPORT 4

// ---------------- GEMM tiling ----------------
#define BM 256
#define BK 32
#define STAGES 4
#define APITCH 36                              // padded pitch (floats): 144B
#define PITCHB (APITCH * 4)                    // 144 bytes
#define A_STAGE_BYTES (BM * PITCHB)            // 36864
#define B_STAGE_BYTES (OUT_DIM * PITCHB)       // 9216
#define STAGE_BYTES (A_STAGE_BYTES + B_STAGE_BYTES)
#define SPLITK 4                               // one relation per CTA
#define K_ITERS (N_NODES / BK)                 // 256
#define GEMM_SMEM (STAGES * STAGE_BYTES)       // 184,320 B -> 1 CTA/SM

// ---------------- device scratch (no allocs allowed) ----------------
__device__ __align__(1024) float g_YT[SUPPORT * OUT_DIM * N_NODES];     // 8 MB
__device__ __align__(1024) float g_part[SPLITK * N_NODES * OUT_DIM];    // 8 MB

// ---------------- helpers ----------------
__device__ __forceinline__ uint32_t smem_u32(const void* p) {
    uint32_t a;
    asm("{ .reg .u64 t; cvta.to.shared.u64 t, %1; cvt.u32.u64 %0, t; }" : "=r"(a) : "l"(p));
    return a;
}
#define CP_ASYNC16(dst_u32, src_ptr) \
    asm volatile("cp.async.cg.shared.global [%0], [%1], 16;" :: "r"(dst_u32), "l"(src_ptr) : "memory")
#define CP_COMMIT() asm volatile("cp.async.commit_group;" ::: "memory")
#define CP_WAIT(n)  asm volatile("cp.async.wait_group %0;" :: "n"(n) : "memory")

#define LDSM_X4(r0, r1, r2, r3, addr) \
    asm volatile("ldmatrix.sync.aligned.m8n8.x4.shared.b16 {%0,%1,%2,%3}, [%4];" \
        : "=r"(r0), "=r"(r1), "=r"(r2), "=r"(r3) : "r"(addr))

#define CVT_TF32(r) asm("cvt.rna.tf32.f32 %0, %0;" : "+r"(r))

#define MMA_TF32(c, a, b0, b1) \
    asm volatile("mma.sync.aligned.m16n8k8.row.col.f32.tf32.tf32.f32 " \
        "{%0,%1,%2,%3}, {%4,%5,%6,%7}, {%8,%9}, {%0,%1,%2,%3};" \
        : "+f"((c)[0]), "+f"((c)[1]), "+f"((c)[2]), "+f"((c)[3]) \
        : "r"((a)[0]), "r"((a)[1]), "r"((a)[2]), "r"((a)[3]), "r"(b0), "r"(b1))

// ---------------- kernel 1: Y^T[s][n][k] = sum_i X[k,i] * V_s[i,n] ----------------
__global__ void y_kernel(const float* __restrict__ X,
                         const float* __restrict__ Kmat,
                         const float* __restrict__ comp,
                         float* __restrict__ YT)
{
    __shared__ float Vs[IN_DIM][OUT_DIM + 1];
    __shared__ float Xs[64][IN_DIM + 1];
    const int s  = blockIdx.y;
    const int j0 = blockIdx.x * 64;
    const float c0 = comp[s * 2 + 0];
    const float c1 = comp[s * 2 + 1];

    for (int idx = threadIdx.x; idx < IN_DIM * OUT_DIM; idx += blockDim.x) {
        int i = idx >> 6, o = idx & 63;
        Vs[i][o] = c0 * Kmat[i * OUT_DIM + o] + c1 * Kmat[(IN_DIM + i) * OUT_DIM + o];
    }
    for (int idx = threadIdx.x; idx < 64 * IN_DIM; idx += blockDim.x) {
        int j = idx >> 6, i = idx & 63;
        Xs[j][i] = X[(size_t)(j0 + j) * IN_DIM + i];
    }
    __syncthreads();

    const int jq = (threadIdx.x & 15) * 4;
    const int oq = (threadIdx.x >> 4) * 4;
    float acc[4][4] = {};
    #pragma unroll 8
    for (int i = 0; i < IN_DIM; i++) {
        float xv[4], vv[4];
        #pragma unroll
        for (int a = 0; a < 4; a++) xv[a] = Xs[jq + a][i];
        #pragma unroll
        for (int b = 0; b < 4; b++) vv[b] = Vs[i][oq + b];
        #pragma unroll
        for (int a = 0; a < 4; a++)
            #pragma unroll
            for (int b = 0; b < 4; b++)
                acc[a][b] = fmaf(xv[a], vv[b], acc[a][b]);
    }

    uint32_t* yt_u = reinterpret_cast<uint32_t*>(YT);
    #pragma unroll
    for (int b = 0; b < 4; b++) {
        #pragma unroll
        for (int a = 0; a < 4; a++) {
            uint32_t t;
            asm("cvt.rna.tf32.f32 %0, %1;" : "=r"(t) : "f"(acc[a][b]));   // pre-round to tf32
            yt_u[((size_t)s * OUT_DIM + oq + b) * N_NODES + j0 + jq + a] = t;
        }
    }
}

// ---------------- kernel 2: raw mma.sync tf32 GEMM, BM=256, 1 relation / CTA ----------------
__global__ void __launch_bounds__(256, 1)
rgcn_gemm_kernel(const float* __restrict__ A,
                 const float* __restrict__ YT,
                 float* __restrict__ part)
{
    extern __shared__ float sm[];
    const uint32_t sm_base = smem_u32(sm);

    const int tid  = threadIdx.x;
    const int wid  = tid >> 5;
    const int lane = tid & 31;
    const int m0   = blockIdx.x * BM;
    const int s    = blockIdx.y;                // relation == split-K index

    // warp grid: 4 (M) x 2 (N); each warp 64 x 32
    const int mbase = (wid & 3) * 64;
    const int nbase = (wid >> 2) * 32;

    const int lrow  = lane & 7;
    const int ltile = lane >> 3;

    // A frag (m16 x k8) x4-tile offsets for 4 m-tiles
    uint32_t aoff[4];
    #pragma unroll
    for (int i = 0; i < 4; i++)
        aoff[i] = (uint32_t)((mbase + 16 * i + lrow + 8 * (ltile & 1)) * PITCHB
                             + 16 * (ltile >> 1));
    // B frag (n16 x k8) x4-tile offsets for 2 n-pairs
    uint32_t boff[2];
    #pragma unroll
    for (int p = 0; p < 2; p++)
        boff[p] = (uint32_t)((nbase + 16 * p + lrow + 8 * (ltile >> 1)) * PITCHB
                             + 16 * (ltile & 1));

    float c[4][4][4];
    #pragma unroll
    for (int i = 0; i < 4; i++)
        #pragma unroll
        for (int j = 0; j < 4; j++)
            #pragma unroll
            for (int r = 0; r < 4; r++) c[i][j][r] = 0.0f;

    const float* Abase = A  + ((size_t)s * N_NODES + m0) * N_NODES;
    const float* Bbase = YT + ((size_t)s * OUT_DIM) * N_NODES;

    auto issue = [&](int it) {
        const int st = it & (STAGES - 1);
        const int k0 = it << 5;
        const uint32_t a_s = sm_base + (uint32_t)(st * STAGE_BYTES);
        const uint32_t b_s = a_s + (uint32_t)A_STAGE_BYTES;
        const float* Ab = Abase + k0;
        const float* Bb = Bbase + k0;
        #pragma unroll
        for (int i = 0; i < 8; i++) {           // 2048 float4 of A
            int v   = tid + i * 256;
            int row = v >> 3;
            int cc  = (v & 7) * 4;
            CP_ASYNC16(a_s + (uint32_t)(row * PITCHB + cc * 4), Ab + (size_t)row * N_NODES + cc);
        }
        #pragma unroll
        for (int i = 0; i < 2; i++) {           // 512 float4 of B
            int v   = tid + i * 256;
            int row = v >> 3;
            int cc  = (v & 7) * 4;
            CP_ASYNC16(b_s + (uint32_t)(row * PITCHB + cc * 4), Bb + (size_t)row * N_NODES + cc);
        }
    };

    #pragma unroll
    for (int p = 0; p < STAGES - 1; p++) { issue(p); CP_COMMIT(); }

    uint32_t af[2][4][4];   // [buf][mtile][reg]
    uint32_t bf[2][2][4];   // [buf][npair][reg]

    for (int it = 0; it < K_ITERS; ++it) {
        CP_WAIT(STAGES - 2);
        __syncthreads();

        const int nx = it + STAGES - 1;
        if (nx < K_ITERS) issue(nx);
        CP_COMMIT();

        const uint32_t sa = sm_base + (uint32_t)((it & (STAGES - 1)) * STAGE_BYTES);
        const uint32_t sb = sa + (uint32_t)A_STAGE_BYTES;

        // preload kk=0 fragments
        #pragma unroll
        for (int i = 0; i < 4; i++)
            LDSM_X4(af[0][i][0], af[0][i][1], af[0][i][2], af[0][i][3], sa + aoff[i]);
        #pragma unroll
        for (int p = 0; p < 2; p++)
            LDSM_X4(bf[0][p][0], bf[0][p][1], bf[0][p][2], bf[0][p][3], sb + boff[p]);

        #pragma unroll
        for (int kk = 0; kk < 4; kk++) {
            const int cur = kk & 1, nxt = cur ^ 1;
            if (kk < 3) {
                const uint32_t ko = (uint32_t)((kk + 1) * 32);
                #pragma unroll
                for (int i = 0; i < 4; i++)
                    LDSM_X4(af[nxt][i][0], af[nxt][i][1], af[nxt][i][2], af[nxt][i][3],
                            sa + aoff[i] + ko);
                #pragma unroll
                for (int p = 0; p < 2; p++)
                    LDSM_X4(bf[nxt][p][0], bf[nxt][p][1], bf[nxt][p][2], bf[nxt][p][3],
                            sb + boff[p] + ko);
            }
            // round A to tf32 (B pre-rounded in g_YT)
            #pragma unroll
            for (int i = 0; i < 4; i++)
                #pragma unroll
                for (int r = 0; r < 4; r++) CVT_TF32(af[cur][i][r]);

            #pragma unroll
            for (int i = 0; i < 4; i++) {
                #pragma unroll
                for (int jn = 0; jn < 4; jn++) {
                    const int p = jn >> 1, q = jn & 1;
                    MMA_TF32(c[i][jn], af[cur][i], bf[cur][p][2 * q], bf[cur][p][2 * q + 1]);
                }
            }
        }
    }

    // ---- write partial tile to global (float2 per fragment half) ----
    float* pbase = part + (size_t)s * N_NODES * OUT_DIM + (size_t)m0 * OUT_DIM;
    const int g = lane >> 2, q2 = (lane & 3) * 2;
    #pragma unroll
    for (int i = 0; i < 4; i++) {
        #pragma unroll
        for (int jn = 0; jn < 4; jn++) {
            const int row = mbase + 16 * i + g;
            const int col = nbase + 8 * jn + q2;
            float2 v0 = make_float2(c[i][jn][0], c[i][jn][1]);
            float2 v1 = make_float2(c[i][jn][2], c[i][jn][3]);
            *reinterpret_cast<float2*>(pbase + (size_t)row * OUT_DIM + col)       = v0;
            *reinterpret_cast<float2*>(pbase + (size_t)(row + 8) * OUT_DIM + col) = v1;
        }
    }
}

// ---------------- kernel 3: reduce + bias + relu ----------------
__global__ void reduce_kernel(const float* __restrict__ part,
                              const float* __restrict__ bias,
                              float* __restrict__ out)
{
    const int v = blockIdx.x * blockDim.x + threadIdx.x;   // float4 index
    const int idx = v * 4;
    const int c = idx & (OUT_DIM - 1);
    float4 r;
    float4 p0 = *reinterpret_cast<const float4*>(part + idx);
    float4 p1 = *reinterpret_cast<const float4*>(part + 1ull * N_NODES * OUT_DIM + idx);
    float4 p2 = *reinterpret_cast<const float4*>(part + 2ull * N_NODES * OUT_DIM + idx);
    float4 p3 = *reinterpret_cast<const float4*>(part + 3ull * N_NODES * OUT_DIM + idx);
    r.x = fmaxf((p0.x + p1.x) + (p2.x + p3.x) + __ldg(bias + c + 0), 0.0f);
    r.y = fmaxf((p0.y + p1.y) + (p2.y + p3.y) + __ldg(bias + c + 1), 0.0f);
    r.z = fmaxf((p0.z + p1.z) + (p2.z + p3.z) + __ldg(bias + c + 2), 0.0f);
    r.w = fmaxf((p0.w + p1.w) + (p2.w + p3.w) + __ldg(bias + c + 3), 0.0f);
    *reinterpret_cast<float4*>(out + idx) = r;
}

// ---------------- host launcher ----------------
extern "C" void kernel_launch(void* const* d_in, const int* in_sizes, int n_in,
                              void* d_out, int out_size)
{
    const float* features = (const float*)d_in[0];
    const float* A        = (const float*)d_in[1];
    const float* kern     = (const float*)d_in[2];
    const float* comp     = (const float*)d_in[3];
    const float* bias     = (const float*)d_in[4];
    float* out = (float*)d_out;

    float* yt = nullptr;
    float* part = nullptr;
    cudaGetSymbolAddress((void**)&yt, g_YT);
    cudaGetSymbolAddress((void**)&part, g_part);

    // 1) Y^T = (X @ V_s)^T, tf32-pre-rounded
    y_kernel<<<dim3(N_NODES / 64, SUPPORT), 256>>>(features, kern, comp, yt);

    // 2) GEMM into partials (BM=256, one relation per CTA, 1 CTA/SM, one wave)
    cudaFuncSetAttribute(rgcn_gemm_kernel,
                         cudaFuncAttributeMaxDynamicSharedMemorySize, GEMM_SMEM);
    rgcn_gemm_kernel<<<dim3(N_NODES / BM, SPLITK), 256, GEMM_SMEM>>>(A, yt, part);

    // 3) reduce partials + bias + relu
    reduce_kernel<<<(N_NODES * OUT_DIM / 4) / 256, 256>>>(part, bias, out);
}

// round 7
// speedup vs baseline: 1.4338x; 1.4338x over previous
#include <cuda_runtime.h>
#include <cstdint>

// ---------------- problem constants ----------------
#define N_NODES 8192
#define KFULL   8192
#define IN_DIM  64
#define OUT_DIM 64
#define SUPPORT 4
#define NB      2                              // num bases

// ---------------- GEMM tiling ----------------
#define BM 128
#define BK 32
#define KSPLIT 2
#define KHALF (KFULL / KSPLIT)                 // 4096
#define K_ITERS (KHALF / BK)                   // 128
#define APITCH 36                              // padded pitch (floats): 144B
#define PITCHB (APITCH * 4)
#define C_TILE_BYTES (BM * PITCHB)             // 18432 per basis
#define CBUF_BYTES (NB * C_TILE_BYTES)         // 36864
#define B_TILE_BYTES (OUT_DIM * PITCHB)        // 9216 per basis
#define BBUF_BYTES (NB * B_TILE_BYTES)         // 18432
#define SMEM_B_OFF (2 * CBUF_BYTES)
#define GEMM_SMEM (2 * CBUF_BYTES + 2 * BBUF_BYTES)   // 110,592 B

// ---------------- device scratch (no allocs allowed) ----------------
__device__ __align__(1024) float g_ZT[NB * OUT_DIM * KFULL];            // 4 MB: ZT[b][n][k]
__device__ __align__(1024) float g_part[KSPLIT * N_NODES * OUT_DIM];    // 4 MB

// ---------------- helpers ----------------
__device__ __forceinline__ uint32_t smem_u32(const void* p) {
    uint32_t a;
    asm("{ .reg .u64 t; cvta.to.shared.u64 t, %1; cvt.u32.u64 %0, t; }" : "=r"(a) : "l"(p));
    return a;
}
#define CP_ASYNC16(dst_u32, src_ptr) \
    asm volatile("cp.async.cg.shared.global [%0], [%1], 16;" :: "r"(dst_u32), "l"(src_ptr) : "memory")
#define CP_COMMIT() asm volatile("cp.async.commit_group;" ::: "memory")
#define CP_WAIT(n)  asm volatile("cp.async.wait_group %0;" :: "n"(n) : "memory")

#define LDSM_X4(r0, r1, r2, r3, addr) \
    asm volatile("ldmatrix.sync.aligned.m8n8.x4.shared.b16 {%0,%1,%2,%3}, [%4];" \
        : "=r"(r0), "=r"(r1), "=r"(r2), "=r"(r3) : "r"(addr))

#define STS128(addr, x, y, z, w) \
    asm volatile("st.shared.v4.b32 [%0], {%1,%2,%3,%4};" \
        :: "r"(addr), "r"(x), "r"(y), "r"(z), "r"(w) : "memory")

#define MMA_TF32(c, a, b0, b1) \
    asm volatile("mma.sync.aligned.m16n8k8.row.col.f32.tf32.tf32.f32 " \
        "{%0,%1,%2,%3}, {%4,%5,%6,%7}, {%8,%9}, {%0,%1,%2,%3};" \
        : "+f"((c)[0]), "+f"((c)[1]), "+f"((c)[2]), "+f"((c)[3]) \
        : "r"((a)[0]), "r"((a)[1]), "r"((a)[2]), "r"((a)[3]), "r"(b0), "r"(b1))

__device__ __forceinline__ uint32_t f2tf32(float f) {
    uint32_t u;
    asm("cvt.rna.tf32.f32 %0, %1;" : "=r"(u) : "f"(f));
    return u;
}

// ---------------- kernel 1: ZT[b][n][k] = sum_i X[k,i] * K_b[i,n] ----------------
__global__ void y_kernel(const float* __restrict__ X,
                         const float* __restrict__ Kmat,
                         float* __restrict__ ZT)
{
    __shared__ float Vs[IN_DIM][OUT_DIM + 1];
    __shared__ float Xs[64][IN_DIM + 1];
    const int b  = blockIdx.y;                  // basis
    const int j0 = blockIdx.x * 64;

    for (int idx = threadIdx.x; idx < IN_DIM * OUT_DIM; idx += blockDim.x) {
        int i = idx >> 6, o = idx & 63;
        Vs[i][o] = Kmat[(b * IN_DIM + i) * OUT_DIM + o];
    }
    for (int idx = threadIdx.x; idx < 64 * IN_DIM; idx += blockDim.x) {
        int j = idx >> 6, i = idx & 63;
        Xs[j][i] = X[(size_t)(j0 + j) * IN_DIM + i];
    }
    __syncthreads();

    const int jq = (threadIdx.x & 15) * 4;
    const int oq = (threadIdx.x >> 4) * 4;
    float acc[4][4] = {};
    #pragma unroll 8
    for (int i = 0; i < IN_DIM; i++) {
        float xv[4], vv[4];
        #pragma unroll
        for (int a = 0; a < 4; a++) xv[a] = Xs[jq + a][i];
        #pragma unroll
        for (int q = 0; q < 4; q++) vv[q] = Vs[i][oq + q];
        #pragma unroll
        for (int a = 0; a < 4; a++)
            #pragma unroll
            for (int q = 0; q < 4; q++)
                acc[a][q] = fmaf(xv[a], vv[q], acc[a][q]);
    }

    uint32_t* zt_u = reinterpret_cast<uint32_t*>(ZT);
    #pragma unroll
    for (int q = 0; q < 4; q++)
        #pragma unroll
        for (int a = 0; a < 4; a++)
            zt_u[((size_t)(b * OUT_DIM) + oq + q) * KFULL + j0 + jq + a] =
                f2tf32(acc[a][q]);
}

// ---------------- kernel 2: combined-basis tf32 GEMM ----------------
// part[kh][m,n] = sum_b sum_{k in half kh} C_b[m,k] * Z_b[k,n],
//   C_b combined in registers from the 4 relation slices of A.
__global__ void __launch_bounds__(256, 1)
rgcn_gemm_kernel(const float* __restrict__ A,
                 const float* __restrict__ ZT,
                 const float* __restrict__ comp,
                 float* __restrict__ part)
{
    extern __shared__ float sm[];
    const uint32_t sm_base = smem_u32(sm);

    const int tid  = threadIdx.x;
    const int wid  = tid >> 5;
    const int lane = tid & 31;
    const int m0   = blockIdx.x * BM;
    const int kh   = blockIdx.y;
    const size_t kbase0 = (size_t)kh * KHALF;

    // warp grid: 4 (M) x 2 (N); each warp 32x32 per basis
    const int mbase = (wid & 3) * 32;
    const int nbase = (wid >> 2) * 32;
    const int lrow  = lane & 7;
    const int ltile = lane >> 3;

    uint32_t aoff[2];
    #pragma unroll
    for (int i = 0; i < 2; i++)
        aoff[i] = (uint32_t)((mbase + 16 * i + lrow + 8 * (ltile & 1)) * PITCHB
                             + 16 * (ltile >> 1));
    uint32_t boff[2];
    #pragma unroll
    for (int p = 0; p < 2; p++)
        boff[p] = (uint32_t)((nbase + 16 * p + lrow + 8 * (ltile >> 1)) * PITCHB
                             + 16 * (ltile & 1));

    // comp coefficients: cb[b][s]
    float cb[NB][SUPPORT];
    #pragma unroll
    for (int s = 0; s < SUPPORT; s++)
        #pragma unroll
        for (int b = 0; b < NB; b++)
            cb[b][s] = __ldg(comp + s * NB + b);

    // accumulators: [basis][mtile][n8][4]
    float c[NB][2][4][4];
    #pragma unroll
    for (int b = 0; b < NB; b++)
        #pragma unroll
        for (int i = 0; i < 2; i++)
            #pragma unroll
            for (int j = 0; j < 4; j++)
                #pragma unroll
                for (int r = 0; r < 4; r++) c[b][i][j][r] = 0.0f;

    // A LDG addressing: thread owns row r = tid>>3 (+32p), col chunk (tid&7)*4
    const int arow = tid >> 3;
    const int acol = (tid & 7) * 4;
    const float4* ap[SUPPORT];
    #pragma unroll
    for (int s = 0; s < SUPPORT; s++)
        ap[s] = reinterpret_cast<const float4*>(
            A + ((size_t)s * KFULL + m0 + arow) * KFULL + kbase0 + acol);
    const size_t APSTEP = (size_t)32 * (KFULL / 4);   // +32 rows, in float4

    // C staging STS addresses (per p, per basis)
    const uint32_t c_sts0 = (uint32_t)(arow * PITCHB + acol * 4);

    // B (ZT) cp.async: thread handles rows {r, r+32} for each basis, r = tid>>3
    const float* zsrc0 = ZT + (size_t)arow * KFULL + kbase0 + acol;
    const uint32_t b_sts0 = (uint32_t)(arow * PITCHB + acol * 4);

    float4 areg[SUPPORT][4];
    auto ldgA = [&](int it) {
        const size_t kofs = (size_t)(it * (BK / 4));   // float4 step per iter
        #pragma unroll
        for (int s = 0; s < SUPPORT; s++)
            #pragma unroll
            for (int p = 0; p < 4; p++)
                areg[s][p] = __ldg(ap[s] + kofs + (size_t)p * APSTEP);
    };

    auto issueB = [&](int it) {
        const uint32_t bs = sm_base + SMEM_B_OFF + (uint32_t)((it & 1) * BBUF_BYTES);
        const size_t kofs = (size_t)it * BK;
        #pragma unroll
        for (int b = 0; b < NB; b++)
            #pragma unroll
            for (int h = 0; h < 2; h++) {
                const float* src = zsrc0 + ((size_t)(b * OUT_DIM + h * 32) * KFULL) + kofs;
                const uint32_t dst = bs + (uint32_t)(b * B_TILE_BYTES + h * 32 * PITCHB) + b_sts0;
                CP_ASYNC16(dst, src);
            }
    };

    // prologue
    ldgA(0);
    issueB(0); CP_COMMIT();

    for (int it = 0; it < K_ITERS; ++it) {
        // ---- combine A relations -> C_b (tf32) -> smem staging ----
        const uint32_t cs = sm_base + (uint32_t)((it & 1) * CBUF_BYTES);
        #pragma unroll
        for (int p = 0; p < 4; p++) {
            const float4 a0 = areg[0][p], a1 = areg[1][p], a2 = areg[2][p], a3 = areg[3][p];
            #pragma unroll
            for (int b = 0; b < NB; b++) {
                float ox = fmaf(cb[b][3], a3.x, fmaf(cb[b][2], a2.x, fmaf(cb[b][1], a1.x, cb[b][0] * a0.x)));
                float oy = fmaf(cb[b][3], a3.y, fmaf(cb[b][2], a2.y, fmaf(cb[b][1], a1.y, cb[b][0] * a0.y)));
                float oz = fmaf(cb[b][3], a3.z, fmaf(cb[b][2], a2.z, fmaf(cb[b][1], a1.z, cb[b][0] * a0.z)));
                float ow = fmaf(cb[b][3], a3.w, fmaf(cb[b][2], a2.w, fmaf(cb[b][1], a1.w, cb[b][0] * a0.w)));
                STS128(cs + (uint32_t)(b * C_TILE_BYTES + p * 32 * PITCHB) + c_sts0,
                       f2tf32(ox), f2tf32(oy), f2tf32(oz), f2tf32(ow));
            }
        }

        // ---- next loads in flight ----
        if (it + 1 < K_ITERS) {
            ldgA(it + 1);
            issueB(it + 1); CP_COMMIT();
            CP_WAIT(1);
        } else {
            CP_WAIT(0);
        }
        __syncthreads();

        // ---- MMA over both bases ----
        const uint32_t csb = sm_base + (uint32_t)((it & 1) * CBUF_BYTES);
        const uint32_t bsb = sm_base + SMEM_B_OFF + (uint32_t)((it & 1) * BBUF_BYTES);
        #pragma unroll
        for (int b = 0; b < NB; b++) {
            const uint32_t ca = csb + (uint32_t)(b * C_TILE_BYTES);
            const uint32_t ba = bsb + (uint32_t)(b * B_TILE_BYTES);
            #pragma unroll
            for (int kk = 0; kk < 4; kk++) {
                const uint32_t ko = (uint32_t)(kk * 32);
                uint32_t af[2][4], bf[2][4];
                #pragma unroll
                for (int i = 0; i < 2; i++)
                    LDSM_X4(af[i][0], af[i][1], af[i][2], af[i][3], ca + aoff[i] + ko);
                #pragma unroll
                for (int p = 0; p < 2; p++)
                    LDSM_X4(bf[p][0], bf[p][1], bf[p][2], bf[p][3], ba + boff[p] + ko);
                #pragma unroll
                for (int i = 0; i < 2; i++) {
                    #pragma unroll
                    for (int jn = 0; jn < 4; jn++) {
                        const int p = jn >> 1, q = jn & 1;
                        MMA_TF32(c[b][i][jn], af[i], bf[p][2 * q], bf[p][2 * q + 1]);
                    }
                }
            }
        }
    }

    // ---- epilogue: sum bases, write partial ----
    float* pbase = part + (size_t)kh * N_NODES * OUT_DIM + (size_t)m0 * OUT_DIM;
    const int g = lane >> 2, q2 = (lane & 3) * 2;
    #pragma unroll
    for (int i = 0; i < 2; i++) {
        #pragma unroll
        for (int jn = 0; jn < 4; jn++) {
            const int row = mbase + 16 * i + g;
            const int col = nbase + 8 * jn + q2;
            float2 v0 = make_float2(c[0][i][jn][0] + c[1][i][jn][0],
                                    c[0][i][jn][1] + c[1][i][jn][1]);
            float2 v1 = make_float2(c[0][i][jn][2] + c[1][i][jn][2],
                                    c[0][i][jn][3] + c[1][i][jn][3]);
            *reinterpret_cast<float2*>(pbase + (size_t)row * OUT_DIM + col)       = v0;
            *reinterpret_cast<float2*>(pbase + (size_t)(row + 8) * OUT_DIM + col) = v1;
        }
    }
}

// ---------------- kernel 3: reduce + bias + relu ----------------
__global__ void reduce_kernel(const float* __restrict__ part,
                              const float* __restrict__ bias,
                              float* __restrict__ out)
{
    const int v = blockIdx.x * blockDim.x + threadIdx.x;   // float4 index
    const int idx = v * 4;
    const int c = idx & (OUT_DIM - 1);
    float4 p0 = *reinterpret_cast<const float4*>(part + idx);
    float4 p1 = *reinterpret_cast<const float4*>(part + (size_t)N_NODES * OUT_DIM + idx);
    float4 r;
    r.x = fmaxf(p0.x + p1.x + __ldg(bias + c + 0), 0.0f);
    r.y = fmaxf(p0.y + p1.y + __ldg(bias + c + 1), 0.0f);
    r.z = fmaxf(p0.z + p1.z + __ldg(bias + c + 2), 0.0f);
    r.w = fmaxf(p0.w + p1.w + __ldg(bias + c + 3), 0.0f);
    *reinterpret_cast<float4*>(out + idx) = r;
}

// ---------------- host launcher ----------------
extern "C" void kernel_launch(void* const* d_in, const int* in_sizes, int n_in,
                              void* d_out, int out_size)
{
    const float* features = (const float*)d_in[0];
    const float* A        = (const float*)d_in[1];
    const float* kern     = (const float*)d_in[2];
    const float* comp     = (const float*)d_in[3];
    const float* bias     = (const float*)d_in[4];
    float* out = (float*)d_out;

    float* zt = nullptr;
    float* pt = nullptr;
    cudaGetSymbolAddress((void**)&zt, g_ZT);
    cudaGetSymbolAddress((void**)&pt, g_part);

    // 1) ZT[b] = (X @ K_b)^T, tf32-pre-rounded
    y_kernel<<<dim3(KFULL / 64, NB), 256>>>(features, kern, zt);

    // 2) combined-basis GEMM into K-split partials
    cudaFuncSetAttribute(rgcn_gemm_kernel,
                         cudaFuncAttributeMaxDynamicSharedMemorySize, GEMM_SMEM);
    rgcn_gemm_kernel<<<dim3(N_NODES / BM, KSPLIT), 256, GEMM_SMEM>>>(A, zt, comp, pt);

    // 3) reduce partials + bias + relu
    reduce_kernel<<<(N_NODES * OUT_DIM / 4) / 256, 256>>>(pt, bias, out);
}